// round 15
// baseline (speedup 1.0000x reference)
#include <cuda_runtime.h>
#include <cuda_fp16.h>
#include <cstdint>

using std::uint32_t;

#define NNODES 50000
#define NEDGES 800000
#define D_IN   128
#define D_H    192
#define D_K    64
#define NB     64
#define HID_DIM 256
#define OUT_DIM 10

// Scratch (static device globals; allocation is forbidden).
__device__ __align__(16) __half g_H[NNODES * D_H];     // fp16 features
__device__ __align__(16) __half g_AGG[NNODES * D_H];   // fp16 aggregation
__device__ __align__(16) __half g_Wt0[D_H * D_IN];     // layer0 Wt[n][k]
__device__ __align__(16) __half g_Wt1[D_H * D_H];      // layer1 Wt[n][k]
__device__ float g_bias0[D_H];
__device__ float g_bias1[D_H];
__device__ float g_POOL[NB * D_H];
__device__ float g_HID[NB * HID_DIM];
__device__ int   g_arrive[1024];        // per-x arrival counters (self-resetting)

// ---------------------------------------------------------------------------
__global__ void zero_pool_kernel() {
    const int i = blockIdx.x * blockDim.x + threadIdx.x;
    if (i < NB * D_H) g_POOL[i] = 0.f;
}

// Merged weight/bias conversion for BOTH layers.
// Wt[n][k] = W_{n/64}[k][n%64] (fp16), bias[n] (fp32).
__global__ void convert_w_all(
    const float* __restrict__ W00, const float* __restrict__ b00,
    const float* __restrict__ W01, const float* __restrict__ b01,
    const float* __restrict__ W02, const float* __restrict__ b02,
    const float* __restrict__ W10, const float* __restrict__ b10,
    const float* __restrict__ W11, const float* __restrict__ b11,
    const float* __restrict__ W12, const float* __restrict__ b12)
{
    const int i = blockIdx.x * blockDim.x + threadIdx.x;
    if (i < D_H * D_IN) {
        int n = i / D_IN, k = i % D_IN;
        const float* __restrict__ W = (n < 64) ? W00 : ((n < 128) ? W01 : W02);
        g_Wt0[i] = __float2half(W[k * D_K + (n & 63)]);
    }
    if (i < D_H * D_H) {
        int n = i / D_H, k = i % D_H;
        const float* __restrict__ W = (n < 64) ? W10 : ((n < 128) ? W11 : W12);
        g_Wt1[i] = __float2half(W[k * D_K + (n & 63)]);
    }
    if (i < D_H) {
        const float* __restrict__ c0 = (i < 64) ? b00 : ((i < 128) ? b01 : b02);
        const float* __restrict__ c1 = (i < 64) ? b10 : ((i < 128) ? b11 : b12);
        g_bias0[i] = c0[i & 63];
        g_bias1[i] = c1[i & 63];
    }
}

// ---------------------------------------------------------------------------
// ldmatrix helpers
// ---------------------------------------------------------------------------
__device__ __forceinline__ void ldsm_x4(
    uint32_t& r0, uint32_t& r1, uint32_t& r2, uint32_t& r3, uint32_t addr)
{
    asm volatile("ldmatrix.sync.aligned.m8n8.x4.shared.b16 {%0,%1,%2,%3}, [%4];"
                 : "=r"(r0), "=r"(r1), "=r"(r2), "=r"(r3) : "r"(addr));
}
__device__ __forceinline__ void ldsm_x2(
    uint32_t& r0, uint32_t& r1, uint32_t addr)
{
    asm volatile("ldmatrix.sync.aligned.m8n8.x2.shared.b16 {%0,%1}, [%2];"
                 : "=r"(r0), "=r"(r1) : "r"(addr));
}

__device__ __forceinline__ void mma_16816(
    float& c0, float& c1, float& c2, float& c3,
    uint32_t a0, uint32_t a1, uint32_t a2, uint32_t a3,
    uint32_t b0, uint32_t b1)
{
    asm volatile(
        "mma.sync.aligned.m16n8k16.row.col.f32.f16.f16.f32 "
        "{%0,%1,%2,%3}, {%4,%5,%6,%7}, {%8,%9}, {%0,%1,%2,%3};"
        : "+f"(c0), "+f"(c1), "+f"(c2), "+f"(c3)
        : "r"(a0), "r"(a1), "r"(a2), "r"(a3), "r"(b0), "r"(b1));
}

// ---------------------------------------------------------------------------
// Tensor-core concat-GEMM, N-split: block (x, y) computes
//   g_H[node0:node0+64, y*96:(y+1)*96] = relu?(in) @ Wt^T + bias   (fp16)
// 256 threads = 8 warps (2m x 4n). Warp tile m32 x n24. ldmatrix fragments.
// Dynamic smem: Bs[96][K+8] + As[64][K+8].
// Second y-block per x (arrival counter) zeroes this x's g_AGG rows.
// ---------------------------------------------------------------------------
template <int K, int SRC>
__global__ void __launch_bounds__(256) mma_gemm_kernel(const float* __restrict__ X)
{
    constexpr int BM = 64;
    constexpr int BN = 96;
    constexpr int KP = K + 8;                       // padded row (halves)
    constexpr int C8 = K / 8;                       // 16B chunks per row

    extern __shared__ __align__(16) __half smem[];
    __half* Bs = smem;                              // [BN][KP]
    __half* As = smem + BN * KP;                    // [BM][KP]

    const int tid   = threadIdx.x;
    const int node0 = blockIdx.x * BM;
    const int ny    = blockIdx.y;                   // 0 or 1
    const int ncol0 = ny * BN;                      // global col base

    const __half* __restrict__ Wt = (SRC == 0) ? g_Wt0 : g_Wt1;
    const float*  __restrict__ bi = (SRC == 0) ? g_bias0 : g_bias1;

    // ---- stage B tile (96 rows of this half) + A tile into smem ----
    for (int idx = tid; idx < (BN + BM) * C8; idx += 256) {
        if (idx < BN * C8) {
            int row = idx / C8, c8 = idx % C8;
            uint4 v = *reinterpret_cast<const uint4*>(
                Wt + (size_t)(ncol0 + row) * K + c8 * 8);
            *reinterpret_cast<uint4*>(&Bs[row * KP + c8 * 8]) = v;
        } else {
            int a   = idx - BN * C8;
            int row = a / C8, c8 = a % C8;
            int gn  = node0 + row;
            uint4 v = make_uint4(0u, 0u, 0u, 0u);
            if (gn < NNODES) {
                if (SRC == 0) {
                    const float4 f0 = *reinterpret_cast<const float4*>(
                        X + (size_t)gn * K + c8 * 8);
                    const float4 f1 = *reinterpret_cast<const float4*>(
                        X + (size_t)gn * K + c8 * 8 + 4);
                    __half2* h2 = reinterpret_cast<__half2*>(&v);
                    h2[0] = __floats2half2_rn(f0.x, f0.y);
                    h2[1] = __floats2half2_rn(f0.z, f0.w);
                    h2[2] = __floats2half2_rn(f1.x, f1.y);
                    h2[3] = __floats2half2_rn(f1.z, f1.w);
                } else {
                    v = *reinterpret_cast<const uint4*>(
                        g_AGG + (size_t)gn * K + c8 * 8);
                    __half2* h2 = reinterpret_cast<__half2*>(&v);
                    const __half2 z2 = __float2half2_rn(0.f);
#pragma unroll
                    for (int j = 0; j < 4; j++) h2[j] = __hmax2(h2[j], z2);
                }
            }
            *reinterpret_cast<uint4*>(&As[row * KP + c8 * 8]) = v;
        }
    }
    __syncthreads();                                // all staging reads done

    // ---- arrival counter: second y-block per x zeroes the AGG rows ----
    __shared__ int s_do_zero;
    if (tid == 0) {
        int old = atomicAdd(&g_arrive[blockIdx.x], 1);
        s_do_zero = (old == 1);
        if (old == 1) g_arrive[blockIdx.x] = 0;     // reset for next launch
    }
    __syncthreads();
    if (s_do_zero) {
        constexpr int CZ = D_H / 8;
        const uint4 zero = make_uint4(0u, 0u, 0u, 0u);
        for (int idx = tid; idx < BM * CZ; idx += 256) {
            int row = idx / CZ, c8 = idx % CZ;
            int gn  = node0 + row;
            if (gn < NNODES)
                *reinterpret_cast<uint4*>(
                    g_AGG + (size_t)gn * D_H + c8 * 8) = zero;
        }
    }

    const int wid  = tid >> 5, lane = tid & 31;
    const int wm   = wid >> 2;                      // 0..1
    const int wn   = wid & 3;                       // 0..3
    const int m0   = wm * 32;
    const int n0   = wn * 24;                       // local col base
    const int gid  = lane >> 2, tig = lane & 3;

    // ldmatrix per-lane base addresses (bytes)
    const uint32_t As_base = (uint32_t)__cvta_generic_to_shared(As);
    const uint32_t Bs_base = (uint32_t)__cvta_generic_to_shared(Bs);
    const int lane7 = lane & 7;
    const int lj    = lane >> 3;                    // 0..3

    uint32_t a_addr[2];
#pragma unroll
    for (int mt = 0; mt < 2; mt++) {
        int row = m0 + mt * 16 + lane7 + (lj & 1) * 8;
        int col = (lj >> 1) * 8;
        a_addr[mt] = As_base + (uint32_t)(row * KP + col) * 2u;
    }
    uint32_t b_addr[3];
#pragma unroll
    for (int t = 0; t < 3; t++) {
        int row = n0 + t * 8 + lane7;
        int col = (lj & 1) * 8;                     // lanes>=16 ignored by x2
        b_addr[t] = Bs_base + (uint32_t)(row * KP + col) * 2u;
    }

    float c[2][3][4];
#pragma unroll
    for (int mt = 0; mt < 2; mt++)
#pragma unroll
        for (int t = 0; t < 3; t++)
#pragma unroll
            for (int j = 0; j < 4; j++) c[mt][t][j] = 0.f;

#pragma unroll
    for (int k0 = 0; k0 < K; k0 += 16) {
        const uint32_t koff = (uint32_t)k0 * 2u;    // bytes
        uint32_t a[2][4];
        ldsm_x4(a[0][0], a[0][1], a[0][2], a[0][3], a_addr[0] + koff);
        ldsm_x4(a[1][0], a[1][1], a[1][2], a[1][3], a_addr[1] + koff);
        uint32_t b[3][2];
#pragma unroll
        for (int t = 0; t < 3; t++)
            ldsm_x2(b[t][0], b[t][1], b_addr[t] + koff);
#pragma unroll
        for (int t = 0; t < 3; t++)
#pragma unroll
            for (int mt = 0; mt < 2; mt++)
                mma_16816(c[mt][t][0], c[mt][t][1], c[mt][t][2], c[mt][t][3],
                          a[mt][0], a[mt][1], a[mt][2], a[mt][3],
                          b[t][0], b[t][1]);
    }

    // ---- epilogue: bias + fp16 pack + store ----
#pragma unroll
    for (int mt = 0; mt < 2; mt++) {
        const int r0 = node0 + m0 + mt * 16 + gid;
        const int r1 = r0 + 8;
#pragma unroll
        for (int t = 0; t < 3; t++) {
            const int colp = ncol0 + n0 + t * 8 + tig * 2;
            float2 bias = *reinterpret_cast<const float2*>(&bi[colp]);
            if (r0 < NNODES) {
                *reinterpret_cast<__half2*>(g_H + (size_t)r0 * D_H + colp) =
                    __floats2half2_rn(c[mt][t][0] + bias.x, c[mt][t][1] + bias.y);
            }
            if (r1 < NNODES) {
                *reinterpret_cast<__half2*>(g_H + (size_t)r1 * D_H + colp) =
                    __floats2half2_rn(c[mt][t][2] + bias.x, c[mt][t][3] + bias.y);
            }
        }
    }
}

// ---------------------------------------------------------------------------
// Edge scatter: AGG[dst, coff:coff+64] += H[src, coff:coff+64]   (fp16)
// 8 threads per edge; one red.global.add.noftz.v4.f16x2 each (8 halves).
// ---------------------------------------------------------------------------
__device__ __forceinline__ void red_add_v4_f16x2(__half* p, uint4 v) {
    asm volatile("red.global.add.noftz.v4.f16x2 [%0], {%1, %2, %3, %4};"
                 :: "l"(p), "r"(v.x), "r"(v.y), "r"(v.z), "r"(v.w)
                 : "memory");
}

__global__ void __launch_bounds__(256) scatter_kernel(
    const int* __restrict__ m0, const int* __restrict__ m1,
    const int* __restrict__ m2)
{
    const int* __restrict__ m =
        (blockIdx.y == 0) ? m0 : (blockIdx.y == 1 ? m1 : m2);
    const int coff = blockIdx.y * D_K;

    const int tid = threadIdx.x;
    const int e   = blockIdx.x * 32 + (tid >> 3);
    const int l   = tid & 7;
    if (e >= NEDGES) return;

    const int dst = m[e];
    const int src = m[NEDGES + e];

    const uint4 v = *reinterpret_cast<const uint4*>(
        g_H + (size_t)src * D_H + coff + l * 8);
    red_add_v4_f16x2(g_AGG + (size_t)dst * D_H + coff + l * 8, v);
}

// ---------------------------------------------------------------------------
// Pooling: POOL[batch_idx[n], c] += relu(AGG[n, c]).  (sorted batch_idx)
// ---------------------------------------------------------------------------
__global__ void __launch_bounds__(192) pool_kernel(
    const int* __restrict__ batch_idx)
{
    constexpr int CHUNK = 128;
    __shared__ int sb[CHUNK];

    const int tid   = threadIdx.x;
    const int node0 = blockIdx.x * CHUNK;

    for (int j = tid; j < CHUNK; j += 192) {
        int n = node0 + j;
        sb[j] = (n < NNODES) ? batch_idx[n] : -1;
    }
    __syncthreads();

    int   cur = -1;
    float acc = 0.f;
    for (int j = 0; j < CHUNK; j++) {
        int b = sb[j];
        if (b < 0) break;
        if (b != cur) {
            if (cur >= 0) atomicAdd(&g_POOL[cur * D_H + tid], acc);
            cur = b;
            acc = 0.f;
        }
        float v = __half2float(g_AGG[(size_t)(node0 + j) * D_H + tid]);
        acc += fmaxf(v, 0.f);
    }
    if (cur >= 0) atomicAdd(&g_POOL[cur * D_H + tid], acc);
}

// ---------------------------------------------------------------------------
// MLP head
// ---------------------------------------------------------------------------
__global__ void __launch_bounds__(HID_DIM) mlp1_kernel(
    const float* __restrict__ A1, const float* __restrict__ ba1)
{
    __shared__ float sp[D_H];
    const int b = blockIdx.x;
    const int t = threadIdx.x;
    for (int k = t; k < D_H; k += HID_DIM) sp[k] = g_POOL[b * D_H + k];
    __syncthreads();

    float acc = ba1[t];
    for (int k = 0; k < D_H; k++) acc += sp[k] * A1[k * HID_DIM + t];
    g_HID[b * HID_DIM + t] = fmaxf(acc, 0.f);
}

__global__ void __launch_bounds__(NB * OUT_DIM) mlp2_kernel(
    const float* __restrict__ A2, const float* __restrict__ ba2,
    float* __restrict__ OUT)
{
    const int t = threadIdx.x;
    const int b = t / OUT_DIM;
    const int o = t % OUT_DIM;
    float acc = ba2[o];
    for (int k = 0; k < HID_DIM; k++)
        acc += g_HID[b * HID_DIM + k] * A2[k * OUT_DIM + o];
    OUT[b * OUT_DIM + o] = acc;
}

// ---------------------------------------------------------------------------
extern "C" void kernel_launch(void* const* d_in, const int* in_sizes, int n_in,
                              void* d_out, int out_size)
{
    const float* x         = (const float*)d_in[0];
    const int*   map00     = (const int*)d_in[1];
    const int*   map01     = (const int*)d_in[2];
    const int*   map02     = (const int*)d_in[3];
    const int*   map10     = (const int*)d_in[4];
    const int*   map11     = (const int*)d_in[5];
    const int*   map12     = (const int*)d_in[6];
    const int*   batch_idx = (const int*)d_in[7];
    // d_in[8] = batch_size (compile-time NB)
    const float* W00 = (const float*)d_in[9];
    const float* b00 = (const float*)d_in[10];
    const float* W01 = (const float*)d_in[11];
    const float* b01 = (const float*)d_in[12];
    const float* W02 = (const float*)d_in[13];
    const float* b02 = (const float*)d_in[14];
    const float* W10 = (const float*)d_in[15];
    const float* b10 = (const float*)d_in[16];
    const float* W11 = (const float*)d_in[17];
    const float* b11 = (const float*)d_in[18];
    const float* W12 = (const float*)d_in[19];
    const float* b12 = (const float*)d_in[20];
    const float* A1  = (const float*)d_in[21];
    const float* ba1 = (const float*)d_in[22];
    const float* A2  = (const float*)d_in[23];
    const float* ba2 = (const float*)d_in[24];
    float* out = (float*)d_out;

    const int gemm_blocks    = (NNODES + 63) / 64;
    const int scatter_blocks = (NEDGES + 31) / 32;
    const int pool_blocks    = (NNODES + 127) / 128;
    const int convw_blocks   = (D_H * D_H + 255) / 256;

    // Dynamic smem: Bs[96][K+8] + As[64][K+8], fp16.
    const int SMEM0 = (96 + 64) * (D_IN + 8) * 2;    // 43520 B -> 5 blocks/SM
    const int SMEM1 = (96 + 64) * (D_H + 8) * 2;     // 64000 B -> 3 blocks/SM
    cudaFuncSetAttribute(mma_gemm_kernel<D_IN, 0>,
                         cudaFuncAttributeMaxDynamicSharedMemorySize, SMEM0);
    cudaFuncSetAttribute(mma_gemm_kernel<D_H, 1>,
                         cudaFuncAttributeMaxDynamicSharedMemorySize, SMEM1);

    // ---- weights (both layers, one kernel) ----
    convert_w_all<<<convw_blocks, 256>>>(W00, b00, W01, b01, W02, b02,
                                         W10, b10, W11, b11, W12, b12);

    // ---- layer 0 (AGG zeroing fused into GEMM via arrival counter) ----
    mma_gemm_kernel<D_IN, 0><<<dim3(gemm_blocks, 2), 256, SMEM0>>>(x);
    scatter_kernel<<<dim3(scatter_blocks, 3), 256>>>(map00, map01, map02);

    // ---- layer 1 ----
    mma_gemm_kernel<D_H, 1><<<dim3(gemm_blocks, 2), 256, SMEM1>>>(nullptr);
    scatter_kernel<<<dim3(scatter_blocks, 3), 256>>>(map10, map11, map12);

    // ---- pooling ----
    zero_pool_kernel<<<(NB * D_H + 255) / 256, 256>>>();
    pool_kernel<<<pool_blocks, 192>>>(batch_idx);

    // ---- MLP head ----
    mlp1_kernel<<<NB, HID_DIM>>>(A1, ba1);
    mlp2_kernel<<<1, NB * OUT_DIM>>>(A2, ba2, out);
}

// round 17
// speedup vs baseline: 1.0090x; 1.0090x over previous
#include <cuda_runtime.h>
#include <cuda_fp16.h>
#include <cstdint>

using std::uint32_t;

#define NNODES 50000
#define NEDGES 800000
#define D_IN   128
#define D_H    192
#define D_K    64
#define NB     64
#define HID_DIM 256
#define OUT_DIM 10

#define BM_T   64
#define NXT    ((NNODES + BM_T - 1) / BM_T)   // 782 x-tiles

// Scratch (static device globals; allocation is forbidden).
__device__ __align__(16) __half g_H[NNODES * D_H];     // fp16 features
__device__ __align__(16) __half g_AGG[NNODES * D_H];   // fp16 aggregation
__device__ __align__(16) __half g_Wt0[D_H * D_IN];     // layer0 Wt[n][k]
__device__ __align__(16) __half g_Wt1[D_H * D_H];      // layer1 Wt[n][k]
__device__ float g_bias0[D_H];
__device__ float g_bias1[D_H];
__device__ float g_POOL[NB * D_H];
__device__ float g_HID[NB * HID_DIM];
__device__ int   g_arrive[NXT];         // per-x arrival counters (self-resetting)

// ---------------------------------------------------------------------------
__global__ void zero_pool_kernel() {
    const int i = blockIdx.x * blockDim.x + threadIdx.x;
    if (i < NB * D_H) g_POOL[i] = 0.f;
}

// Merged weight/bias conversion for BOTH layers.
// Wt[n][k] = W_{n/64}[k][n%64] (fp16), bias[n] (fp32).
__global__ void convert_w_all(
    const float* __restrict__ W00, const float* __restrict__ b00,
    const float* __restrict__ W01, const float* __restrict__ b01,
    const float* __restrict__ W02, const float* __restrict__ b02,
    const float* __restrict__ W10, const float* __restrict__ b10,
    const float* __restrict__ W11, const float* __restrict__ b11,
    const float* __restrict__ W12, const float* __restrict__ b12)
{
    const int i = blockIdx.x * blockDim.x + threadIdx.x;
    if (i < D_H * D_IN) {
        int n = i / D_IN, k = i % D_IN;
        const float* __restrict__ W = (n < 64) ? W00 : ((n < 128) ? W01 : W02);
        g_Wt0[i] = __float2half(W[k * D_K + (n & 63)]);
    }
    if (i < D_H * D_H) {
        int n = i / D_H, k = i % D_H;
        const float* __restrict__ W = (n < 64) ? W10 : ((n < 128) ? W11 : W12);
        g_Wt1[i] = __float2half(W[k * D_K + (n & 63)]);
    }
    if (i < D_H) {
        const float* __restrict__ c0 = (i < 64) ? b00 : ((i < 128) ? b01 : b02);
        const float* __restrict__ c1 = (i < 64) ? b10 : ((i < 128) ? b11 : b12);
        g_bias0[i] = c0[i & 63];
        g_bias1[i] = c1[i & 63];
    }
}

// ---------------------------------------------------------------------------
__device__ __forceinline__ void mma_16816(
    float& c0, float& c1, float& c2, float& c3,
    uint32_t a0, uint32_t a1, uint32_t a2, uint32_t a3,
    uint32_t b0, uint32_t b1)
{
    asm volatile(
        "mma.sync.aligned.m16n8k16.row.col.f32.f16.f16.f32 "
        "{%0,%1,%2,%3}, {%4,%5,%6,%7}, {%8,%9}, {%0,%1,%2,%3};"
        : "+f"(c0), "+f"(c1), "+f"(c2), "+f"(c3)
        : "r"(a0), "r"(a1), "r"(a2), "r"(a3), "r"(b0), "r"(b1));
}

// ---------------------------------------------------------------------------
// Tensor-core concat-GEMM, N-split + tile loop: block (bx, y) loops over
// x-tiles xt = bx, bx+GX, ... and computes
//   g_H[xt*64:(xt+1)*64, y*96:(y+1)*96] = relu?(in) @ Wt^T + bias   (fp16)
// B tile is staged ONCE per block; A is staged per x-tile.
// 256 threads = 8 warps (2m x 4n). Warp tile m32 x n24. Scalar LDS fragments.
// Second y-block per x (arrival counter) zeroes this x's g_AGG rows.
// ---------------------------------------------------------------------------
template <int K, int SRC>
__global__ void __launch_bounds__(256) mma_gemm_kernel(const float* __restrict__ X)
{
    constexpr int BM = BM_T;
    constexpr int BN = 96;
    constexpr int KP = K + 8;                       // padded row (halves)
    constexpr int C8 = K / 8;                       // 16B chunks per row

    extern __shared__ __align__(16) __half smem[];
    __half* Bs = smem;                              // [BN][KP]
    __half* As = smem + BN * KP;                    // [BM][KP]

    const int tid   = threadIdx.x;
    const int ny    = blockIdx.y;                   // 0 or 1
    const int ncol0 = ny * BN;                      // global col base

    const __half* __restrict__ Wt = (SRC == 0) ? g_Wt0 : g_Wt1;
    const float*  __restrict__ bi = (SRC == 0) ? g_bias0 : g_bias1;

    // ---- stage B tile once per block ----
    for (int idx = tid; idx < BN * C8; idx += 256) {
        int row = idx / C8, c8 = idx % C8;
        uint4 v = *reinterpret_cast<const uint4*>(
            Wt + (size_t)(ncol0 + row) * K + c8 * 8);
        *reinterpret_cast<uint4*>(&Bs[row * KP + c8 * 8]) = v;
    }

    const int wid  = tid >> 5, lane = tid & 31;
    const int wm   = wid >> 2;                      // 0..1
    const int wn   = wid & 3;                       // 0..3
    const int m0   = wm * 32;
    const int n0   = wn * 24;                       // local col base
    const int gid  = lane >> 2, tig = lane & 3;

    for (int xt = blockIdx.x; xt < NXT; xt += gridDim.x) {
        const int node0 = xt * BM;

        __syncthreads();   // previous iteration's As reads done (and B ready)

        // ---- stage A tile (fp16) into smem, zero-fill OOR rows ----
        for (int idx = tid; idx < BM * C8; idx += 256) {
            int row = idx / C8, c8 = idx % C8;
            int gn  = node0 + row;
            uint4 v = make_uint4(0u, 0u, 0u, 0u);
            if (gn < NNODES) {
                if (SRC == 0) {
                    const float4 f0 = *reinterpret_cast<const float4*>(
                        X + (size_t)gn * K + c8 * 8);
                    const float4 f1 = *reinterpret_cast<const float4*>(
                        X + (size_t)gn * K + c8 * 8 + 4);
                    __half2* h2 = reinterpret_cast<__half2*>(&v);
                    h2[0] = __floats2half2_rn(f0.x, f0.y);
                    h2[1] = __floats2half2_rn(f0.z, f0.w);
                    h2[2] = __floats2half2_rn(f1.x, f1.y);
                    h2[3] = __floats2half2_rn(f1.z, f1.w);
                } else {
                    v = *reinterpret_cast<const uint4*>(
                        g_AGG + (size_t)gn * K + c8 * 8);
                    __half2* h2 = reinterpret_cast<__half2*>(&v);
                    const __half2 z2 = __float2half2_rn(0.f);
#pragma unroll
                    for (int j = 0; j < 4; j++) h2[j] = __hmax2(h2[j], z2);
                }
            }
            *reinterpret_cast<uint4*>(&As[row * KP + c8 * 8]) = v;
        }
        __syncthreads();                            // staging reads done

        // ---- arrival counter: second y-block per x zeroes the AGG rows ----
        __shared__ int s_do_zero;
        if (tid == 0) {
            int old = atomicAdd(&g_arrive[xt], 1);
            s_do_zero = (old == 1);
            if (old == 1) g_arrive[xt] = 0;         // reset for next launch
        }
        __syncthreads();
        if (s_do_zero) {
            constexpr int CZ = D_H / 8;
            const uint4 zero = make_uint4(0u, 0u, 0u, 0u);
            for (int idx = tid; idx < BM * CZ; idx += 256) {
                int row = idx / CZ, c8 = idx % CZ;
                int gn  = node0 + row;
                if (gn < NNODES)
                    *reinterpret_cast<uint4*>(
                        g_AGG + (size_t)gn * D_H + c8 * 8) = zero;
            }
        }

        float c[2][3][4];
#pragma unroll
        for (int mt = 0; mt < 2; mt++)
#pragma unroll
            for (int t = 0; t < 3; t++)
#pragma unroll
                for (int j = 0; j < 4; j++) c[mt][t][j] = 0.f;

#pragma unroll
        for (int k0 = 0; k0 < K; k0 += 16) {
            const int ka = k0 + tig * 2;
            uint32_t a[2][4];
#pragma unroll
            for (int mt = 0; mt < 2; mt++) {
                const int ar0 = (m0 + mt * 16 + gid) * KP;
                const int ar1 = ar0 + 8 * KP;
                a[mt][0] = *reinterpret_cast<const uint32_t*>(&As[ar0 + ka]);
                a[mt][1] = *reinterpret_cast<const uint32_t*>(&As[ar1 + ka]);
                a[mt][2] = *reinterpret_cast<const uint32_t*>(&As[ar0 + ka + 8]);
                a[mt][3] = *reinterpret_cast<const uint32_t*>(&As[ar1 + ka + 8]);
            }
#pragma unroll
            for (int t = 0; t < 3; t++) {
                const int n = n0 + t * 8 + gid;     // local B row
                uint32_t b0 = *reinterpret_cast<const uint32_t*>(&Bs[n * KP + ka]);
                uint32_t b1 = *reinterpret_cast<const uint32_t*>(&Bs[n * KP + ka + 8]);
#pragma unroll
                for (int mt = 0; mt < 2; mt++)
                    mma_16816(c[mt][t][0], c[mt][t][1], c[mt][t][2], c[mt][t][3],
                              a[mt][0], a[mt][1], a[mt][2], a[mt][3], b0, b1);
            }
        }

        // ---- epilogue: bias + fp16 pack + store ----
#pragma unroll
        for (int mt = 0; mt < 2; mt++) {
            const int r0 = node0 + m0 + mt * 16 + gid;
            const int r1 = r0 + 8;
#pragma unroll
            for (int t = 0; t < 3; t++) {
                const int colp = ncol0 + n0 + t * 8 + tig * 2;
                float2 bias = *reinterpret_cast<const float2*>(&bi[colp]);
                if (r0 < NNODES) {
                    *reinterpret_cast<__half2*>(g_H + (size_t)r0 * D_H + colp) =
                        __floats2half2_rn(c[mt][t][0] + bias.x, c[mt][t][1] + bias.y);
                }
                if (r1 < NNODES) {
                    *reinterpret_cast<__half2*>(g_H + (size_t)r1 * D_H + colp) =
                        __floats2half2_rn(c[mt][t][2] + bias.x, c[mt][t][3] + bias.y);
                }
            }
        }
    }
}

// ---------------------------------------------------------------------------
// Edge scatter: AGG[dst, coff:coff+64] += H[src, coff:coff+64]   (fp16)
// 8 threads per edge; one red.global.add.noftz.v4.f16x2 each (8 halves).
// ---------------------------------------------------------------------------
__device__ __forceinline__ void red_add_v4_f16x2(__half* p, uint4 v) {
    asm volatile("red.global.add.noftz.v4.f16x2 [%0], {%1, %2, %3, %4};"
                 :: "l"(p), "r"(v.x), "r"(v.y), "r"(v.z), "r"(v.w)
                 : "memory");
}

__global__ void __launch_bounds__(256) scatter_kernel(
    const int* __restrict__ m0, const int* __restrict__ m1,
    const int* __restrict__ m2)
{
    const int* __restrict__ m =
        (blockIdx.y == 0) ? m0 : (blockIdx.y == 1 ? m1 : m2);
    const int coff = blockIdx.y * D_K;

    const int tid = threadIdx.x;
    const int e   = blockIdx.x * 32 + (tid >> 3);
    const int l   = tid & 7;
    if (e >= NEDGES) return;

    const int dst = m[e];
    const int src = m[NEDGES + e];

    const uint4 v = *reinterpret_cast<const uint4*>(
        g_H + (size_t)src * D_H + coff + l * 8);
    red_add_v4_f16x2(g_AGG + (size_t)dst * D_H + coff + l * 8, v);
}

// ---------------------------------------------------------------------------
// Pooling: POOL[batch_idx[n], c] += relu(AGG[n, c]).  (sorted batch_idx)
// ---------------------------------------------------------------------------
__global__ void __launch_bounds__(192) pool_kernel(
    const int* __restrict__ batch_idx)
{
    constexpr int CHUNK = 128;
    __shared__ int sb[CHUNK];

    const int tid   = threadIdx.x;
    const int node0 = blockIdx.x * CHUNK;

    for (int j = tid; j < CHUNK; j += 192) {
        int n = node0 + j;
        sb[j] = (n < NNODES) ? batch_idx[n] : -1;
    }
    __syncthreads();

    int   cur = -1;
    float acc = 0.f;
    for (int j = 0; j < CHUNK; j++) {
        int b = sb[j];
        if (b < 0) break;
        if (b != cur) {
            if (cur >= 0) atomicAdd(&g_POOL[cur * D_H + tid], acc);
            cur = b;
            acc = 0.f;
        }
        float v = __half2float(g_AGG[(size_t)(node0 + j) * D_H + tid]);
        acc += fmaxf(v, 0.f);
    }
    if (cur >= 0) atomicAdd(&g_POOL[cur * D_H + tid], acc);
}

// ---------------------------------------------------------------------------
// MLP head
// ---------------------------------------------------------------------------
__global__ void __launch_bounds__(HID_DIM) mlp1_kernel(
    const float* __restrict__ A1, const float* __restrict__ ba1)
{
    __shared__ float sp[D_H];
    const int b = blockIdx.x;
    const int t = threadIdx.x;
    for (int k = t; k < D_H; k += HID_DIM) sp[k] = g_POOL[b * D_H + k];
    __syncthreads();

    float acc = ba1[t];
    for (int k = 0; k < D_H; k++) acc += sp[k] * A1[k * HID_DIM + t];
    g_HID[b * HID_DIM + t] = fmaxf(acc, 0.f);
}

__global__ void __launch_bounds__(NB * OUT_DIM) mlp2_kernel(
    const float* __restrict__ A2, const float* __restrict__ ba2,
    float* __restrict__ OUT)
{
    const int t = threadIdx.x;
    const int b = t / OUT_DIM;
    const int o = t % OUT_DIM;
    float acc = ba2[o];
    for (int k = 0; k < HID_DIM; k++)
        acc += g_HID[b * HID_DIM + k] * A2[k * OUT_DIM + o];
    OUT[b * OUT_DIM + o] = acc;
}

// ---------------------------------------------------------------------------
extern "C" void kernel_launch(void* const* d_in, const int* in_sizes, int n_in,
                              void* d_out, int out_size)
{
    const float* x         = (const float*)d_in[0];
    const int*   map00     = (const int*)d_in[1];
    const int*   map01     = (const int*)d_in[2];
    const int*   map02     = (const int*)d_in[3];
    const int*   map10     = (const int*)d_in[4];
    const int*   map11     = (const int*)d_in[5];
    const int*   map12     = (const int*)d_in[6];
    const int*   batch_idx = (const int*)d_in[7];
    // d_in[8] = batch_size (compile-time NB)
    const float* W00 = (const float*)d_in[9];
    const float* b00 = (const float*)d_in[10];
    const float* W01 = (const float*)d_in[11];
    const float* b01 = (const float*)d_in[12];
    const float* W02 = (const float*)d_in[13];
    const float* b02 = (const float*)d_in[14];
    const float* W10 = (const float*)d_in[15];
    const float* b10 = (const float*)d_in[16];
    const float* W11 = (const float*)d_in[17];
    const float* b11 = (const float*)d_in[18];
    const float* W12 = (const float*)d_in[19];
    const float* b12 = (const float*)d_in[20];
    const float* A1  = (const float*)d_in[21];
    const float* ba1 = (const float*)d_in[22];
    const float* A2  = (const float*)d_in[23];
    const float* ba2 = (const float*)d_in[24];
    float* out = (float*)d_out;

    const int scatter_blocks = (NEDGES + 31) / 32;
    const int pool_blocks    = (NNODES + 127) / 128;
    const int convw_blocks   = (D_H * D_H + 255) / 256;

    // Dynamic smem: Bs[96][K+8] + As[64][K+8], fp16.
    const int SMEM0 = (96 + 64) * (D_IN + 8) * 2;    // 43520 B -> 5 blocks/SM
    const int SMEM1 = (96 + 64) * (D_H + 8) * 2;     // 64000 B -> 3 blocks/SM
    cudaFuncSetAttribute(mma_gemm_kernel<D_IN, 0>,
                         cudaFuncAttributeMaxDynamicSharedMemorySize, SMEM0);
    cudaFuncSetAttribute(mma_gemm_kernel<D_H, 1>,
                         cudaFuncAttributeMaxDynamicSharedMemorySize, SMEM1);

    // One-wave grids (148 SMs): K=128 -> 5 blocks/SM, K=192 -> 3 blocks/SM.
    const int GX0 = 370;   // 370*2 = 740 = 148*5
    const int GX1 = 222;   // 222*2 = 444 = 148*3

    // ---- weights (both layers, one kernel) ----
    convert_w_all<<<convw_blocks, 256>>>(W00, b00, W01, b01, W02, b02,
                                         W10, b10, W11, b11, W12, b12);

    // ---- layer 0 (AGG zeroing fused into GEMM via arrival counter) ----
    mma_gemm_kernel<D_IN, 0><<<dim3(GX0, 2), 256, SMEM0>>>(x);
    scatter_kernel<<<dim3(scatter_blocks, 3), 256>>>(map00, map01, map02);

    // ---- layer 1 ----
    mma_gemm_kernel<D_H, 1><<<dim3(GX1, 2), 256, SMEM1>>>(nullptr);
    scatter_kernel<<<dim3(scatter_blocks, 3), 256>>>(map10, map11, map12);

    // ---- pooling ----
    zero_pool_kernel<<<(NB * D_H + 255) / 256, 256>>>();
    pool_kernel<<<pool_blocks, 192>>>(batch_idx);

    // ---- MLP head ----
    mlp1_kernel<<<NB, HID_DIM>>>(A1, ba1);
    mlp2_kernel<<<1, NB * OUT_DIM>>>(A2, ba2, out);
}